// round 6
// baseline (speedup 1.0000x reference)
#include <cuda_runtime.h>
#include <cuda_bf16.h>
#include <stdint.h>
#include <math_constants.h>

#define BATCH 2
#define SEQ   2048
#define EMB   1024
#define NH    16
#define HD    64
#define TOK   4096
#define QKVF  3072
#define NROWS (BATCH * NH * SEQ)
#define OUT_ELEMS ((size_t)TOK * EMB)

__device__ float g_qkv[(size_t)TOK * QKVF];   // 50 MB scratch
__device__ float g_ao [(size_t)TOK * EMB];    // 16 MB scratch
__device__ float g_rowsum[NROWS];

// ---------------------------------------------------------------------------
// helpers
// ---------------------------------------------------------------------------
__device__ __forceinline__ uint32_t smem_u32(const void* p) {
    uint32_t a;
    asm("{ .reg .u64 t; cvta.to.shared.u64 t, %1; cvt.u32.u64 %0, t; }" : "=r"(a) : "l"(p));
    return a;
}
__device__ __forceinline__ void mma_bf16(float* c, const uint32_t* a, uint32_t b0, uint32_t b1) {
    asm volatile(
        "mma.sync.aligned.m16n8k16.row.col.f32.bf16.bf16.f32 "
        "{%0,%1,%2,%3}, {%4,%5,%6,%7}, {%8,%9}, {%0,%1,%2,%3};"
        : "+f"(c[0]), "+f"(c[1]), "+f"(c[2]), "+f"(c[3])
        : "r"(a[0]), "r"(a[1]), "r"(a[2]), "r"(a[3]), "r"(b0), "r"(b1));
}
__device__ __forceinline__ void ldsm4(uint32_t* r, uint32_t a) {
    asm volatile("ldmatrix.sync.aligned.m8n8.x4.shared.b16 {%0,%1,%2,%3}, [%4];"
        : "=r"(r[0]), "=r"(r[1]), "=r"(r[2]), "=r"(r[3]) : "r"(a));
}
__device__ __forceinline__ void split2(float x, float y, uint32_t& hi, uint32_t& lo) {
    __nv_bfloat16 bx = __float2bfloat16_rn(x), by = __float2bfloat16_rn(y);
    float rx = x - __bfloat162float(bx);
    float ry = y - __bfloat162float(by);
    __nv_bfloat162 h; h.x = bx; h.y = by;
    __nv_bfloat162 l = __floats2bfloat162_rn(rx, ry);
    hi = *reinterpret_cast<uint32_t*>(&h);
    lo = *reinterpret_cast<uint32_t*>(&l);
}

#define STRB 80   // smem row stride: 64B data + 16B pad -> ldmatrix conflict-free

__global__ void zero_rowsum_kernel() {
    g_rowsum[blockIdx.x * 256 + threadIdx.x] = 0.f;
}

// ---------------------------------------------------------------------------
// C[M,N] = A[M,K] @ W[N,K]^T + bias. Block 128x128, BK=32, 8 warps (2x4).
// ---------------------------------------------------------------------------
__global__ void __launch_bounds__(256) mma_gemm_bias(
    const float* __restrict__ A, const float* __restrict__ W,
    const float* __restrict__ bias, float* __restrict__ C, int N, int K)
{
    __shared__ __align__(16) char sAh[128 * STRB];
    __shared__ __align__(16) char sAl[128 * STRB];
    __shared__ __align__(16) char sBh[128 * STRB];
    __shared__ __align__(16) char sBl[128 * STRB];

    const int tid = threadIdx.x;
    const int lane = tid & 31, wid = tid >> 5;
    const int warp_m = wid >> 2, warp_n = wid & 3;
    const int bm = blockIdx.y * 128, bn = blockIdx.x * 128;
    const int row = tid >> 1, kq = (tid & 1) * 16;
    const int r4 = lane >> 2, c4 = lane & 3;
    // ldmatrix per-lane addressing: 16-row group, two 16B k-halves
    const int lrow = ((lane >> 3) & 1) * 8 + (lane & 7);
    const int lkof = (lane >> 4) * 16;

    const uint32_t aAh = smem_u32(sAh), aAl = smem_u32(sAl);
    const uint32_t aBh = smem_u32(sBh), aBl = smem_u32(sBl);

    float acc[4][4][4];
#pragma unroll
    for (int i = 0; i < 4; i++)
#pragma unroll
        for (int j = 0; j < 4; j++)
#pragma unroll
            for (int l = 0; l < 4; l++) acc[i][j][l] = 0.f;

    for (int kt = 0; kt < (K >> 5); kt++) {
        const float* Ap = A + (size_t)(bm + row) * K + kt * 32 + kq;
        const float* Wp = W + (size_t)(bn + row) * K + kt * 32 + kq;
        float4 av[4], wv[4];
#pragma unroll
        for (int i = 0; i < 4; i++) av[i] = *(const float4*)(Ap + i * 4);
#pragma unroll
        for (int i = 0; i < 4; i++) wv[i] = *(const float4*)(Wp + i * 4);
        __syncthreads();
#pragma unroll
        for (int i = 0; i < 4; i++) {
            uint32_t h0, l0, h1, l1;
            split2(av[i].x, av[i].y, h0, l0);
            split2(av[i].z, av[i].w, h1, l1);
            uint32_t off = row * STRB + (kq + i * 4) * 2;
            *(uint2*)(sAh + off) = make_uint2(h0, h1);
            *(uint2*)(sAl + off) = make_uint2(l0, l1);
            split2(wv[i].x, wv[i].y, h0, l0);
            split2(wv[i].z, wv[i].w, h1, l1);
            *(uint2*)(sBh + off) = make_uint2(h0, h1);
            *(uint2*)(sBl + off) = make_uint2(l0, l1);
        }
        __syncthreads();

#pragma unroll
        for (int s = 0; s < 2; s++) {
            const int kb = s * 32;
            uint32_t Ah[4][4], Al[4][4];
#pragma unroll
            for (int fm = 0; fm < 4; fm++) {
                uint32_t off = (uint32_t)(warp_m * 64 + fm * 16 + lrow) * STRB + kb + lkof;
                ldsm4(Ah[fm], aAh + off);
                ldsm4(Al[fm], aAl + off);
            }
#pragma unroll
            for (int fnp = 0; fnp < 2; fnp++) {
                uint32_t off = (uint32_t)(warp_n * 32 + fnp * 16 + lrow) * STRB + kb + lkof;
                uint32_t Bh[4], Bl[4];
                ldsm4(Bh, aBh + off);
                ldsm4(Bl, aBl + off);
                // Bh = {fnA.b0, fnB.b0, fnA.b1, fnB.b1}
#pragma unroll
                for (int fm = 0; fm < 4; fm++) {
                    mma_bf16(acc[fm][fnp * 2 + 0], Ah[fm], Bh[0], Bh[2]);
                    mma_bf16(acc[fm][fnp * 2 + 0], Ah[fm], Bl[0], Bl[2]);
                    mma_bf16(acc[fm][fnp * 2 + 0], Al[fm], Bh[0], Bh[2]);
                    mma_bf16(acc[fm][fnp * 2 + 1], Ah[fm], Bh[1], Bh[3]);
                    mma_bf16(acc[fm][fnp * 2 + 1], Ah[fm], Bl[1], Bl[3]);
                    mma_bf16(acc[fm][fnp * 2 + 1], Al[fm], Bh[1], Bh[3]);
                }
            }
        }
    }

    const int cq = c4 * 2;
#pragma unroll
    for (int fm = 0; fm < 4; fm++) {
#pragma unroll
        for (int fn = 0; fn < 4; fn++) {
            int row0 = bm + warp_m * 64 + fm * 16 + r4;
            int col  = bn + warp_n * 32 + fn * 8 + cq;
            float b0 = bias[col], b1 = bias[col + 1];
            *(float2*)(C + (size_t)row0 * N + col) =
                make_float2(acc[fm][fn][0] + b0, acc[fm][fn][1] + b1);
            *(float2*)(C + (size_t)(row0 + 8) * N + col) =
                make_float2(acc[fm][fn][2] + b0, acc[fm][fn][3] + b1);
        }
    }
}

// ---------------------------------------------------------------------------
// Scores + exp: E = exp(0.125 * Q K^T); atomic row sums. Block 128x128.
// ---------------------------------------------------------------------------
__global__ void __launch_bounds__(256) mma_scores_exp(
    const float* __restrict__ qkv, float* __restrict__ attn)
{
    __shared__ __align__(16) char sAh[128 * STRB];
    __shared__ __align__(16) char sAl[128 * STRB];
    __shared__ __align__(16) char sBh[128 * STRB];
    __shared__ __align__(16) char sBl[128 * STRB];

    const int tid = threadIdx.x;
    const int lane = tid & 31, wid = tid >> 5;
    const int warp_m = wid >> 2, warp_n = wid & 3;
    const int z = blockIdx.z, b = z >> 4, h = z & 15;
    const int bm = blockIdx.y * 128, bn = blockIdx.x * 128;
    const float* Qb = qkv + (size_t)b * SEQ * QKVF + h * HD;
    const float* Kb = Qb + EMB;
    float* Cb = attn + (size_t)z * SEQ * SEQ;
    const int row = tid >> 1, kq = (tid & 1) * 16;
    const int r4 = lane >> 2, c4 = lane & 3;
    const int lrow = ((lane >> 3) & 1) * 8 + (lane & 7);
    const int lkof = (lane >> 4) * 16;

    const uint32_t aAh = smem_u32(sAh), aAl = smem_u32(sAl);
    const uint32_t aBh = smem_u32(sBh), aBl = smem_u32(sBl);

    float acc[4][4][4];
#pragma unroll
    for (int i = 0; i < 4; i++)
#pragma unroll
        for (int j = 0; j < 4; j++)
#pragma unroll
            for (int l = 0; l < 4; l++) acc[i][j][l] = 0.f;

#pragma unroll
    for (int kt = 0; kt < 2; kt++) {
        const float* Ap = Qb + (size_t)(bm + row) * QKVF + kt * 32 + kq;
        const float* Bp = Kb + (size_t)(bn + row) * QKVF + kt * 32 + kq;
        float4 av[4], wv[4];
#pragma unroll
        for (int i = 0; i < 4; i++) av[i] = *(const float4*)(Ap + i * 4);
#pragma unroll
        for (int i = 0; i < 4; i++) wv[i] = *(const float4*)(Bp + i * 4);
        __syncthreads();
#pragma unroll
        for (int i = 0; i < 4; i++) {
            uint32_t h0, l0, h1, l1;
            split2(av[i].x, av[i].y, h0, l0);
            split2(av[i].z, av[i].w, h1, l1);
            uint32_t off = row * STRB + (kq + i * 4) * 2;
            *(uint2*)(sAh + off) = make_uint2(h0, h1);
            *(uint2*)(sAl + off) = make_uint2(l0, l1);
            split2(wv[i].x, wv[i].y, h0, l0);
            split2(wv[i].z, wv[i].w, h1, l1);
            *(uint2*)(sBh + off) = make_uint2(h0, h1);
            *(uint2*)(sBl + off) = make_uint2(l0, l1);
        }
        __syncthreads();

#pragma unroll
        for (int s = 0; s < 2; s++) {
            const int kb = s * 32;
            uint32_t Ah[4][4], Al[4][4];
#pragma unroll
            for (int fm = 0; fm < 4; fm++) {
                uint32_t off = (uint32_t)(warp_m * 64 + fm * 16 + lrow) * STRB + kb + lkof;
                ldsm4(Ah[fm], aAh + off);
                ldsm4(Al[fm], aAl + off);
            }
#pragma unroll
            for (int fnp = 0; fnp < 2; fnp++) {
                uint32_t off = (uint32_t)(warp_n * 32 + fnp * 16 + lrow) * STRB + kb + lkof;
                uint32_t Bh[4], Bl[4];
                ldsm4(Bh, aBh + off);
                ldsm4(Bl, aBl + off);
#pragma unroll
                for (int fm = 0; fm < 4; fm++) {
                    mma_bf16(acc[fm][fnp * 2 + 0], Ah[fm], Bh[0], Bh[2]);
                    mma_bf16(acc[fm][fnp * 2 + 0], Ah[fm], Bl[0], Bl[2]);
                    mma_bf16(acc[fm][fnp * 2 + 0], Al[fm], Bh[0], Bh[2]);
                    mma_bf16(acc[fm][fnp * 2 + 1], Ah[fm], Bh[1], Bh[3]);
                    mma_bf16(acc[fm][fnp * 2 + 1], Ah[fm], Bl[1], Bl[3]);
                    mma_bf16(acc[fm][fnp * 2 + 1], Al[fm], Bh[1], Bh[3]);
                }
            }
        }
    }

    // epilogue: exp, store E, row-sum atomics
#pragma unroll
    for (int fm = 0; fm < 4; fm++) {
        const int row0 = bm + warp_m * 64 + fm * 16 + r4;
        float rs0 = 0.f, rs1 = 0.f;
#pragma unroll
        for (int fn = 0; fn < 4; fn++) {
            float e0 = __expf(acc[fm][fn][0] * 0.125f);
            float e1 = __expf(acc[fm][fn][1] * 0.125f);
            float e2 = __expf(acc[fm][fn][2] * 0.125f);
            float e3 = __expf(acc[fm][fn][3] * 0.125f);
            rs0 += e0 + e1;
            rs1 += e2 + e3;
            int col = bn + warp_n * 32 + fn * 8 + c4 * 2;
            *(float2*)(Cb + (size_t)row0 * SEQ + col)       = make_float2(e0, e1);
            *(float2*)(Cb + (size_t)(row0 + 8) * SEQ + col) = make_float2(e2, e3);
        }
        rs0 += __shfl_xor_sync(0xffffffffu, rs0, 1);
        rs0 += __shfl_xor_sync(0xffffffffu, rs0, 2);
        rs1 += __shfl_xor_sync(0xffffffffu, rs1, 1);
        rs1 += __shfl_xor_sync(0xffffffffu, rs1, 2);
        if (c4 == 0) {
            atomicAdd(&g_rowsum[(size_t)z * SEQ + row0], rs0);
            atomicAdd(&g_rowsum[(size_t)z * SEQ + row0 + 8], rs1);
        }
    }
}

// ---------------------------------------------------------------------------
// AV + normalize: reads E, writes P = E*inv back (during staging), computes
// O = inv * (E @ V) by scaling the accumulator. Block 128x64, 8 warps (4x2).
// ---------------------------------------------------------------------------
__global__ void __launch_bounds__(256) mma_av_norm(
    float* __restrict__ attn, const float* __restrict__ qkv,
    float* __restrict__ out)
{
    __shared__ __align__(16) char sAh[128 * STRB];
    __shared__ __align__(16) char sAl[128 * STRB];
    __shared__ __align__(16) char sBh[64 * STRB];
    __shared__ __align__(16) char sBl[64 * STRB];

    const int tid = threadIdx.x;
    const int lane = tid & 31, wid = tid >> 5;
    const int warp_m = wid >> 1, warp_n = wid & 1;
    const int z = blockIdx.y, b = z >> 4, h = z & 15;
    const int bm = blockIdx.x * 128;
    float* P = attn + (size_t)z * SEQ * SEQ;
    const float* V = qkv + (size_t)b * SEQ * QKVF + 2 * EMB + h * HD;
    float* O = out + (size_t)b * SEQ * EMB + h * HD;
    const int row = tid >> 1, kq = (tid & 1) * 16;
    const int vt = tid >> 3, vd = (tid & 7) * 8;
    const int r4 = lane >> 2, c4 = lane & 3;
    const int lrow = ((lane >> 3) & 1) * 8 + (lane & 7);
    const int lkof = (lane >> 4) * 16;

    const uint32_t aAh = smem_u32(sAh), aAl = smem_u32(sAl);
    const uint32_t aBh = smem_u32(sBh), aBl = smem_u32(sBl);

    // loader-row reciprocal (each thread stages exactly one P row)
    const float inv_l = __frcp_rn(g_rowsum[(size_t)z * SEQ + bm + row]);

    float acc[2][4][4];
#pragma unroll
    for (int i = 0; i < 2; i++)
#pragma unroll
        for (int j = 0; j < 4; j++)
#pragma unroll
            for (int l = 0; l < 4; l++) acc[i][j][l] = 0.f;

    for (int kt = 0; kt < (SEQ >> 5); kt++) {
        float* Pp = P + (size_t)(bm + row) * SEQ + kt * 32 + kq;
        float4 av[4];
#pragma unroll
        for (int i = 0; i < 4; i++) av[i] = *(const float4*)(Pp + i * 4);
        // normalize in registers
#pragma unroll
        for (int i = 0; i < 4; i++) {
            av[i].x *= inv_l; av[i].y *= inv_l; av[i].z *= inv_l; av[i].w *= inv_l;
        }
        const float* Vp = V + (size_t)(kt * 32 + vt) * QKVF + vd;
        float4 vv0 = *(const float4*)(Vp);
        float4 vv1 = *(const float4*)(Vp + 4);

        // write P back (coalesced float4)
#pragma unroll
        for (int i = 0; i < 4; i++) *(float4*)(Pp + i * 4) = av[i];

        __syncthreads();
#pragma unroll
        for (int i = 0; i < 4; i++) {
            uint32_t h0, l0, h1, l1;
            split2(av[i].x, av[i].y, h0, l0);
            split2(av[i].z, av[i].w, h1, l1);
            uint32_t off = row * STRB + (kq + i * 4) * 2;
            *(uint2*)(sAh + off) = make_uint2(h0, h1);
            *(uint2*)(sAl + off) = make_uint2(l0, l1);
        }
        {
            float vals[8] = {vv0.x, vv0.y, vv0.z, vv0.w, vv1.x, vv1.y, vv1.z, vv1.w};
#pragma unroll
            for (int j = 0; j < 8; j++) {
                int d = vd + j;
                __nv_bfloat16 bh = __float2bfloat16_rn(vals[j]);
                float rl = vals[j] - __bfloat162float(bh);
                *(__nv_bfloat16*)(sBh + d * STRB + vt * 2) = bh;
                *(__nv_bfloat16*)(sBl + d * STRB + vt * 2) = __float2bfloat16_rn(rl);
            }
        }
        __syncthreads();

#pragma unroll
        for (int s = 0; s < 2; s++) {
            const int kb = s * 32;
            uint32_t Ah[2][4], Al[2][4];
#pragma unroll
            for (int fm = 0; fm < 2; fm++) {
                uint32_t off = (uint32_t)(warp_m * 32 + fm * 16 + lrow) * STRB + kb + lkof;
                ldsm4(Ah[fm], aAh + off);
                ldsm4(Al[fm], aAl + off);
            }
#pragma unroll
            for (int fnp = 0; fnp < 2; fnp++) {
                uint32_t off = (uint32_t)(warp_n * 32 + fnp * 16 + lrow) * STRB + kb + lkof;
                uint32_t Bh[4], Bl[4];
                ldsm4(Bh, aBh + off);
                ldsm4(Bl, aBl + off);
#pragma unroll
                for (int fm = 0; fm < 2; fm++) {
                    mma_bf16(acc[fm][fnp * 2 + 0], Ah[fm], Bh[0], Bh[2]);
                    mma_bf16(acc[fm][fnp * 2 + 0], Ah[fm], Bl[0], Bl[2]);
                    mma_bf16(acc[fm][fnp * 2 + 0], Al[fm], Bh[0], Bh[2]);
                    mma_bf16(acc[fm][fnp * 2 + 1], Ah[fm], Bh[1], Bh[3]);
                    mma_bf16(acc[fm][fnp * 2 + 1], Ah[fm], Bl[1], Bl[3]);
                    mma_bf16(acc[fm][fnp * 2 + 1], Al[fm], Bh[1], Bh[3]);
                }
            }
        }
    }

    // epilogue: note A was already normalized (P), so acc is final O
    const int cq = c4 * 2;
#pragma unroll
    for (int fm = 0; fm < 2; fm++) {
#pragma unroll
        for (int fn = 0; fn < 4; fn++) {
            int row0 = bm + warp_m * 32 + fm * 16 + r4;
            int col  = warp_n * 32 + fn * 8 + cq;
            *(float2*)(O + (size_t)row0 * EMB + col) =
                make_float2(acc[fm][fn][0], acc[fm][fn][1]);
            *(float2*)(O + (size_t)(row0 + 8) * EMB + col) =
                make_float2(acc[fm][fn][2], acc[fm][fn][3]);
        }
    }
}

// ---------------------------------------------------------------------------
extern "C" void kernel_launch(void* const* d_in, const int* in_sizes, int n_in,
                              void* d_out, int out_size)
{
    const float* x     = (const float*)d_in[0];
    const float* qkv_w = (const float*)d_in[1];
    const float* qkv_b = (const float*)d_in[2];
    const float* out_w = (const float*)d_in[3];
    const float* out_b = (const float*)d_in[4];

    float* out_proj = (float*)d_out;
    float* attn     = (float*)d_out + OUT_ELEMS;

    float* qkv = nullptr;
    float* ao  = nullptr;
    cudaGetSymbolAddress((void**)&qkv, g_qkv);
    cudaGetSymbolAddress((void**)&ao,  g_ao);

    // 1. QKV projection
    mma_gemm_bias<<<dim3(QKVF / 128, TOK / 128), 256>>>(x, qkv_w, qkv_b, qkv, QKVF, EMB);
    // 2. zero rowsums
    zero_rowsum_kernel<<<NROWS / 256, 256>>>();
    // 3. Scores + exp + rowsum
    mma_scores_exp<<<dim3(SEQ / 128, SEQ / 128, BATCH * NH), 256>>>(qkv, attn);
    // 4. AV + normalize (P written in place during staging)
    mma_av_norm<<<dim3(SEQ / 128, BATCH * NH), 256>>>(attn, qkv, ao);
    // 5. Output projection
    mma_gemm_bias<<<dim3(EMB / 128, TOK / 128), 256>>>(ao, out_w, out_b, out_proj, EMB, EMB);
}

// round 8
// speedup vs baseline: 1.0524x; 1.0524x over previous
#include <cuda_runtime.h>
#include <cuda_bf16.h>
#include <stdint.h>
#include <math_constants.h>

#define BATCH 2
#define SEQ   2048
#define EMB   1024
#define NH    16
#define HD    64
#define TOK   4096
#define QKVF  3072
#define OUT_ELEMS ((size_t)TOK * EMB)

__device__ float g_qkv[(size_t)TOK * QKVF];   // 50 MB scratch
__device__ float g_ao [(size_t)TOK * EMB];    // 16 MB scratch

// ---------------------------------------------------------------------------
// helpers
// ---------------------------------------------------------------------------
__device__ __forceinline__ void mma_bf16(float* c, const uint32_t* a, uint32_t b0, uint32_t b1) {
    asm volatile(
        "mma.sync.aligned.m16n8k16.row.col.f32.bf16.bf16.f32 "
        "{%0,%1,%2,%3}, {%4,%5,%6,%7}, {%8,%9}, {%0,%1,%2,%3};"
        : "+f"(c[0]), "+f"(c[1]), "+f"(c[2]), "+f"(c[3])
        : "r"(a[0]), "r"(a[1]), "r"(a[2]), "r"(a[3]), "r"(b0), "r"(b1));
}

__device__ __forceinline__ void split2(float x, float y, uint32_t& hi, uint32_t& lo) {
    __nv_bfloat16 bx = __float2bfloat16_rn(x), by = __float2bfloat16_rn(y);
    float rx = x - __bfloat162float(bx);
    float ry = y - __bfloat162float(by);
    __nv_bfloat162 h; h.x = bx; h.y = by;
    __nv_bfloat162 l = __floats2bfloat162_rn(rx, ry);
    hi = *reinterpret_cast<uint32_t*>(&h);
    lo = *reinterpret_cast<uint32_t*>(&l);
}

#define STRB 72          // smem row stride bytes (32 bf16 + pad)
#define BUF128 (128 * STRB)
#define BUF64  (64 * STRB)

// ---------------------------------------------------------------------------
// C[M,N] = A[M,K] @ W[N,K]^T + bias.  Block 128x128, BK=32, 8 warps (2x4).
// Double-buffered smem: one sync per k-iter, LDG(k+1) overlaps MMA(k).
// ---------------------------------------------------------------------------
__global__ void __launch_bounds__(256) mma_gemm_bias(
    const float* __restrict__ A, const float* __restrict__ W,
    const float* __restrict__ bias, float* __restrict__ C, int N, int K)
{
    __shared__ __align__(16) char sAh[2 * BUF128];
    __shared__ __align__(16) char sAl[2 * BUF128];
    __shared__ __align__(16) char sBh[2 * BUF128];
    __shared__ __align__(16) char sBl[2 * BUF128];

    const int tid = threadIdx.x;
    const int lane = tid & 31, wid = tid >> 5;
    const int warp_m = wid >> 2, warp_n = wid & 3;
    const int bm = blockIdx.y * 128, bn = blockIdx.x * 128;
    const int row = tid >> 1, kq = (tid & 1) * 16;
    const int r4 = lane >> 2, c4 = lane & 3;

    float acc[4][4][4];
#pragma unroll
    for (int i = 0; i < 4; i++)
#pragma unroll
        for (int j = 0; j < 4; j++)
#pragma unroll
            for (int l = 0; l < 4; l++) acc[i][j][l] = 0.f;

    const float* Ab = A + (size_t)(bm + row) * K + kq;
    const float* Wb = W + (size_t)(bn + row) * K + kq;
    const int NIT = K >> 5;

    float4 av[4], wv[4];
#pragma unroll
    for (int i = 0; i < 4; i++) av[i] = *(const float4*)(Ab + i * 4);
#pragma unroll
    for (int i = 0; i < 4; i++) wv[i] = *(const float4*)(Wb + i * 4);

    for (int kt = 0; kt < NIT; kt++) {
        char* bAh = sAh + (kt & 1) * BUF128;
        char* bAl = sAl + (kt & 1) * BUF128;
        char* bBh = sBh + (kt & 1) * BUF128;
        char* bBl = sBl + (kt & 1) * BUF128;
#pragma unroll
        for (int i = 0; i < 4; i++) {
            uint32_t h0, l0, h1, l1;
            split2(av[i].x, av[i].y, h0, l0);
            split2(av[i].z, av[i].w, h1, l1);
            uint32_t off = row * STRB + (kq + i * 4) * 2;
            *(uint2*)(bAh + off) = make_uint2(h0, h1);
            *(uint2*)(bAl + off) = make_uint2(l0, l1);
            split2(wv[i].x, wv[i].y, h0, l0);
            split2(wv[i].z, wv[i].w, h1, l1);
            *(uint2*)(bBh + off) = make_uint2(h0, h1);
            *(uint2*)(bBl + off) = make_uint2(l0, l1);
        }
        __syncthreads();
        if (kt + 1 < NIT) {
#pragma unroll
            for (int i = 0; i < 4; i++) av[i] = *(const float4*)(Ab + (kt + 1) * 32 + i * 4);
#pragma unroll
            for (int i = 0; i < 4; i++) wv[i] = *(const float4*)(Wb + (kt + 1) * 32 + i * 4);
        }

#pragma unroll
        for (int s = 0; s < 2; s++) {
            const int kb = s * 32;
            uint32_t Ah[4][4], Al[4][4];
#pragma unroll
            for (int fm = 0; fm < 4; fm++) {
                uint32_t base = (warp_m * 64 + fm * 16 + r4) * STRB + kb + c4 * 4;
                Ah[fm][0] = *(const uint32_t*)(bAh + base);
                Ah[fm][1] = *(const uint32_t*)(bAh + base + 8 * STRB);
                Ah[fm][2] = *(const uint32_t*)(bAh + base + 16);
                Ah[fm][3] = *(const uint32_t*)(bAh + base + 8 * STRB + 16);
                Al[fm][0] = *(const uint32_t*)(bAl + base);
                Al[fm][1] = *(const uint32_t*)(bAl + base + 8 * STRB);
                Al[fm][2] = *(const uint32_t*)(bAl + base + 16);
                Al[fm][3] = *(const uint32_t*)(bAl + base + 8 * STRB + 16);
            }
#pragma unroll
            for (int fn = 0; fn < 4; fn++) {
                uint32_t bb = (warp_n * 32 + fn * 8 + r4) * STRB + kb + c4 * 4;
                uint32_t Bh0 = *(const uint32_t*)(bBh + bb);
                uint32_t Bh1 = *(const uint32_t*)(bBh + bb + 16);
                uint32_t Bl0 = *(const uint32_t*)(bBl + bb);
                uint32_t Bl1 = *(const uint32_t*)(bBl + bb + 16);
#pragma unroll
                for (int fm = 0; fm < 4; fm++) {
                    mma_bf16(acc[fm][fn], Ah[fm], Bh0, Bh1);
                    mma_bf16(acc[fm][fn], Ah[fm], Bl0, Bl1);
                    mma_bf16(acc[fm][fn], Al[fm], Bh0, Bh1);
                }
            }
        }
    }

    const int cq = c4 * 2;
#pragma unroll
    for (int fm = 0; fm < 4; fm++) {
#pragma unroll
        for (int fn = 0; fn < 4; fn++) {
            int row0 = bm + warp_m * 64 + fm * 16 + r4;
            int col  = bn + warp_n * 32 + fn * 8 + cq;
            float b0 = bias[col], b1 = bias[col + 1];
            *(float2*)(C + (size_t)row0 * N + col) =
                make_float2(acc[fm][fn][0] + b0, acc[fm][fn][1] + b1);
            *(float2*)(C + (size_t)(row0 + 8) * N + col) =
                make_float2(acc[fm][fn][2] + b0, acc[fm][fn][3] + b1);
        }
    }
}

// ---------------------------------------------------------------------------
// Scores: attn[z][q][t] = 0.125 * Q K^T.  2 k-iters, double-buffered.
// ---------------------------------------------------------------------------
__global__ void __launch_bounds__(256) mma_scores(
    const float* __restrict__ qkv, float* __restrict__ attn)
{
    __shared__ __align__(16) char sAh[2 * BUF128];
    __shared__ __align__(16) char sAl[2 * BUF128];
    __shared__ __align__(16) char sBh[2 * BUF128];
    __shared__ __align__(16) char sBl[2 * BUF128];

    const int tid = threadIdx.x;
    const int lane = tid & 31, wid = tid >> 5;
    const int warp_m = wid >> 2, warp_n = wid & 3;
    const int z = blockIdx.z, b = z >> 4, h = z & 15;
    const int bm = blockIdx.y * 128, bn = blockIdx.x * 128;
    const float* Qb = qkv + (size_t)b * SEQ * QKVF + h * HD;
    const float* Kb = Qb + EMB;
    float* Cb = attn + (size_t)z * SEQ * SEQ;
    const int row = tid >> 1, kq = (tid & 1) * 16;
    const int r4 = lane >> 2, c4 = lane & 3;

    float acc[4][4][4];
#pragma unroll
    for (int i = 0; i < 4; i++)
#pragma unroll
        for (int j = 0; j < 4; j++)
#pragma unroll
            for (int l = 0; l < 4; l++) acc[i][j][l] = 0.f;

    const float* Ab = Qb + (size_t)(bm + row) * QKVF + kq;
    const float* Bb = Kb + (size_t)(bn + row) * QKVF + kq;

    float4 av[4], wv[4];
#pragma unroll
    for (int i = 0; i < 4; i++) av[i] = *(const float4*)(Ab + i * 4);
#pragma unroll
    for (int i = 0; i < 4; i++) wv[i] = *(const float4*)(Bb + i * 4);

#pragma unroll
    for (int kt = 0; kt < 2; kt++) {
        char* bAh = sAh + (kt & 1) * BUF128;
        char* bAl = sAl + (kt & 1) * BUF128;
        char* bBh = sBh + (kt & 1) * BUF128;
        char* bBl = sBl + (kt & 1) * BUF128;
#pragma unroll
        for (int i = 0; i < 4; i++) {
            uint32_t h0, l0, h1, l1;
            split2(av[i].x, av[i].y, h0, l0);
            split2(av[i].z, av[i].w, h1, l1);
            uint32_t off = row * STRB + (kq + i * 4) * 2;
            *(uint2*)(bAh + off) = make_uint2(h0, h1);
            *(uint2*)(bAl + off) = make_uint2(l0, l1);
            split2(wv[i].x, wv[i].y, h0, l0);
            split2(wv[i].z, wv[i].w, h1, l1);
            *(uint2*)(bBh + off) = make_uint2(h0, h1);
            *(uint2*)(bBl + off) = make_uint2(l0, l1);
        }
        __syncthreads();
        if (kt == 0) {
#pragma unroll
            for (int i = 0; i < 4; i++) av[i] = *(const float4*)(Ab + 32 + i * 4);
#pragma unroll
            for (int i = 0; i < 4; i++) wv[i] = *(const float4*)(Bb + 32 + i * 4);
        }

#pragma unroll
        for (int s = 0; s < 2; s++) {
            const int kb = s * 32;
            uint32_t Ah[4][4], Al[4][4];
#pragma unroll
            for (int fm = 0; fm < 4; fm++) {
                uint32_t base = (warp_m * 64 + fm * 16 + r4) * STRB + kb + c4 * 4;
                Ah[fm][0] = *(const uint32_t*)(bAh + base);
                Ah[fm][1] = *(const uint32_t*)(bAh + base + 8 * STRB);
                Ah[fm][2] = *(const uint32_t*)(bAh + base + 16);
                Ah[fm][3] = *(const uint32_t*)(bAh + base + 8 * STRB + 16);
                Al[fm][0] = *(const uint32_t*)(bAl + base);
                Al[fm][1] = *(const uint32_t*)(bAl + base + 8 * STRB);
                Al[fm][2] = *(const uint32_t*)(bAl + base + 16);
                Al[fm][3] = *(const uint32_t*)(bAl + base + 8 * STRB + 16);
            }
#pragma unroll
            for (int fn = 0; fn < 4; fn++) {
                uint32_t bb = (warp_n * 32 + fn * 8 + r4) * STRB + kb + c4 * 4;
                uint32_t Bh0 = *(const uint32_t*)(bBh + bb);
                uint32_t Bh1 = *(const uint32_t*)(bBh + bb + 16);
                uint32_t Bl0 = *(const uint32_t*)(bBl + bb);
                uint32_t Bl1 = *(const uint32_t*)(bBl + bb + 16);
#pragma unroll
                for (int fm = 0; fm < 4; fm++) {
                    mma_bf16(acc[fm][fn], Ah[fm], Bh0, Bh1);
                    mma_bf16(acc[fm][fn], Ah[fm], Bl0, Bl1);
                    mma_bf16(acc[fm][fn], Al[fm], Bh0, Bh1);
                }
            }
        }
    }

    const int cq = c4 * 2;
#pragma unroll
    for (int fm = 0; fm < 4; fm++) {
#pragma unroll
        for (int fn = 0; fn < 4; fn++) {
            int row0 = bm + warp_m * 64 + fm * 16 + r4;
            int col  = bn + warp_n * 32 + fn * 8 + cq;
            *(float2*)(Cb + (size_t)row0 * SEQ + col) =
                make_float2(acc[fm][fn][0] * 0.125f, acc[fm][fn][1] * 0.125f);
            *(float2*)(Cb + (size_t)(row0 + 8) * SEQ + col) =
                make_float2(acc[fm][fn][2] * 0.125f, acc[fm][fn][3] * 0.125f);
        }
    }
}

// ---------------------------------------------------------------------------
// AV: O = P @ V.  Block 128x64, BK=32, 8 warps (4x2). Double-buffered.
// ---------------------------------------------------------------------------
__global__ void __launch_bounds__(256) mma_av(
    const float* __restrict__ attn, const float* __restrict__ qkv,
    float* __restrict__ out)
{
    __shared__ __align__(16) char sAh[2 * BUF128];
    __shared__ __align__(16) char sAl[2 * BUF128];
    __shared__ __align__(16) char sBh[2 * BUF64];
    __shared__ __align__(16) char sBl[2 * BUF64];

    const int tid = threadIdx.x;
    const int lane = tid & 31, wid = tid >> 5;
    const int warp_m = wid >> 1, warp_n = wid & 1;
    const int z = blockIdx.y, b = z >> 4, h = z & 15;
    const int bm = blockIdx.x * 128;
    const float* P = attn + (size_t)z * SEQ * SEQ;
    const float* V = qkv + (size_t)b * SEQ * QKVF + 2 * EMB + h * HD;
    float* O = out + (size_t)b * SEQ * EMB + h * HD;
    const int row = tid >> 1, kq = (tid & 1) * 16;
    const int vt = tid >> 3, vd = (tid & 7) * 8;
    const int r4 = lane >> 2, c4 = lane & 3;

    float acc[2][4][4];
#pragma unroll
    for (int i = 0; i < 2; i++)
#pragma unroll
        for (int j = 0; j < 4; j++)
#pragma unroll
            for (int l = 0; l < 4; l++) acc[i][j][l] = 0.f;

    const float* Pb = P + (size_t)(bm + row) * SEQ + kq;
    const float* Vb = V + (size_t)vt * QKVF + vd;

    float4 av[4], vv0, vv1;
#pragma unroll
    for (int i = 0; i < 4; i++) av[i] = *(const float4*)(Pb + i * 4);
    vv0 = *(const float4*)(Vb);
    vv1 = *(const float4*)(Vb + 4);

    const int NIT = SEQ >> 5;
    for (int kt = 0; kt < NIT; kt++) {
        char* bAh = sAh + (kt & 1) * BUF128;
        char* bAl = sAl + (kt & 1) * BUF128;
        char* bBh = sBh + (kt & 1) * BUF64;
        char* bBl = sBl + (kt & 1) * BUF64;
#pragma unroll
        for (int i = 0; i < 4; i++) {
            uint32_t h0, l0, h1, l1;
            split2(av[i].x, av[i].y, h0, l0);
            split2(av[i].z, av[i].w, h1, l1);
            uint32_t off = row * STRB + (kq + i * 4) * 2;
            *(uint2*)(bAh + off) = make_uint2(h0, h1);
            *(uint2*)(bAl + off) = make_uint2(l0, l1);
        }
        {
            float vals[8] = {vv0.x, vv0.y, vv0.z, vv0.w, vv1.x, vv1.y, vv1.z, vv1.w};
#pragma unroll
            for (int j = 0; j < 8; j++) {
                int d = vd + j;
                __nv_bfloat16 bh = __float2bfloat16_rn(vals[j]);
                float rl = vals[j] - __bfloat162float(bh);
                *(__nv_bfloat16*)(bBh + d * STRB + vt * 2) = bh;
                *(__nv_bfloat16*)(bBl + d * STRB + vt * 2) = __float2bfloat16_rn(rl);
            }
        }
        __syncthreads();
        if (kt + 1 < NIT) {
#pragma unroll
            for (int i = 0; i < 4; i++) av[i] = *(const float4*)(Pb + (kt + 1) * 32 + i * 4);
            vv0 = *(const float4*)(Vb + (size_t)(kt + 1) * 32 * QKVF);
            vv1 = *(const float4*)(Vb + (size_t)(kt + 1) * 32 * QKVF + 4);
        }

#pragma unroll
        for (int s = 0; s < 2; s++) {
            const int kb = s * 32;
            uint32_t Ah[2][4], Al[2][4];
#pragma unroll
            for (int fm = 0; fm < 2; fm++) {
                uint32_t base = (warp_m * 32 + fm * 16 + r4) * STRB + kb + c4 * 4;
                Ah[fm][0] = *(const uint32_t*)(bAh + base);
                Ah[fm][1] = *(const uint32_t*)(bAh + base + 8 * STRB);
                Ah[fm][2] = *(const uint32_t*)(bAh + base + 16);
                Ah[fm][3] = *(const uint32_t*)(bAh + base + 8 * STRB + 16);
                Al[fm][0] = *(const uint32_t*)(bAl + base);
                Al[fm][1] = *(const uint32_t*)(bAl + base + 8 * STRB);
                Al[fm][2] = *(const uint32_t*)(bAl + base + 16);
                Al[fm][3] = *(const uint32_t*)(bAl + base + 8 * STRB + 16);
            }
#pragma unroll
            for (int fn = 0; fn < 4; fn++) {
                uint32_t bb = (warp_n * 32 + fn * 8 + r4) * STRB + kb + c4 * 4;
                uint32_t Bh0 = *(const uint32_t*)(bBh + bb);
                uint32_t Bh1 = *(const uint32_t*)(bBh + bb + 16);
                uint32_t Bl0 = *(const uint32_t*)(bBl + bb);
                uint32_t Bl1 = *(const uint32_t*)(bBl + bb + 16);
#pragma unroll
                for (int fm = 0; fm < 2; fm++) {
                    mma_bf16(acc[fm][fn], Ah[fm], Bh0, Bh1);
                    mma_bf16(acc[fm][fn], Ah[fm], Bl0, Bl1);
                    mma_bf16(acc[fm][fn], Al[fm], Bh0, Bh1);
                }
            }
        }
    }

    const int cq = c4 * 2;
#pragma unroll
    for (int fm = 0; fm < 2; fm++) {
#pragma unroll
        for (int fn = 0; fn < 4; fn++) {
            int row0 = bm + warp_m * 32 + fm * 16 + r4;
            int col  = warp_n * 32 + fn * 8 + cq;
            *(float2*)(O + (size_t)row0 * EMB + col) =
                make_float2(acc[fm][fn][0], acc[fm][fn][1]);
            *(float2*)(O + (size_t)(row0 + 8) * EMB + col) =
                make_float2(acc[fm][fn][2], acc[fm][fn][3]);
        }
    }
}

// ---------------------------------------------------------------------------
// Row softmax in place (unchanged from R3).
// ---------------------------------------------------------------------------
__global__ void __launch_bounds__(256) softmax_kernel(float* __restrict__ attn)
{
    __shared__ float sh[8];
    float* p = attn + (size_t)blockIdx.x * SEQ;
    const int t = threadIdx.x;
    const int lane = t & 31, warp = t >> 5;

    float v[8];
    float m = -CUDART_INF_F;
#pragma unroll
    for (int i = 0; i < 8; i++) {
        v[i] = p[t + i * 256];
        m = fmaxf(m, v[i]);
    }
#pragma unroll
    for (int o = 16; o > 0; o >>= 1) m = fmaxf(m, __shfl_xor_sync(0xffffffffu, m, o));
    if (lane == 0) sh[warp] = m;
    __syncthreads();
    if (warp == 0) {
        float mm = sh[lane & 7];
#pragma unroll
        for (int o = 4; o > 0; o >>= 1) mm = fmaxf(mm, __shfl_xor_sync(0xffffffffu, mm, o));
        if (lane == 0) sh[0] = mm;
    }
    __syncthreads();
    const float mx = sh[0];
    __syncthreads();

    float s = 0.f;
#pragma unroll
    for (int i = 0; i < 8; i++) {
        v[i] = __expf(v[i] - mx);
        s += v[i];
    }
#pragma unroll
    for (int o = 16; o > 0; o >>= 1) s += __shfl_xor_sync(0xffffffffu, s, o);
    if (lane == 0) sh[warp] = s;
    __syncthreads();
    if (warp == 0) {
        float ss = sh[lane & 7];
#pragma unroll
        for (int o = 4; o > 0; o >>= 1) ss += __shfl_xor_sync(0xffffffffu, ss, o);
        if (lane == 0) sh[0] = ss;
    }
    __syncthreads();
    const float inv = 1.0f / sh[0];

#pragma unroll
    for (int i = 0; i < 8; i++) p[t + i * 256] = v[i] * inv;
}

// ---------------------------------------------------------------------------
extern "C" void kernel_launch(void* const* d_in, const int* in_sizes, int n_in,
                              void* d_out, int out_size)
{
    const float* x     = (const float*)d_in[0];
    const float* qkv_w = (const float*)d_in[1];
    const float* qkv_b = (const float*)d_in[2];
    const float* out_w = (const float*)d_in[3];
    const float* out_b = (const float*)d_in[4];

    float* out_proj = (float*)d_out;
    float* attn     = (float*)d_out + OUT_ELEMS;

    float* qkv = nullptr;
    float* ao  = nullptr;
    cudaGetSymbolAddress((void**)&qkv, g_qkv);
    cudaGetSymbolAddress((void**)&ao,  g_ao);

    // 1. QKV projection
    mma_gemm_bias<<<dim3(QKVF / 128, TOK / 128), 256>>>(x, qkv_w, qkv_b, qkv, QKVF, EMB);
    // 2. Scores (scaled)
    mma_scores<<<dim3(SEQ / 128, SEQ / 128, BATCH * NH), 256>>>(qkv, attn);
    // 3. Softmax in place
    softmax_kernel<<<BATCH * NH * SEQ, 256>>>(attn);
    // 4. AV
    mma_av<<<dim3(SEQ / 128, BATCH * NH), 256>>>(attn, qkv, ao);
    // 5. Output projection
    mma_gemm_bias<<<dim3(EMB / 128, TOK / 128), 256>>>(ao, out_w, out_b, out_proj, EMB, EMB);
}

// round 10
// speedup vs baseline: 1.1148x; 1.0593x over previous
#include <cuda_runtime.h>
#include <cuda_bf16.h>
#include <stdint.h>
#include <math_constants.h>

#define BATCH 2
#define SEQ   2048
#define EMB   1024
#define NH    16
#define HD    64
#define TOK   4096
#define QKVF  3072
#define NROWS (BATCH * NH * SEQ)
#define OUT_ELEMS ((size_t)TOK * EMB)

__device__ float g_qkv[(size_t)TOK * QKVF];   // 50 MB scratch
__device__ float g_ao [(size_t)TOK * EMB];    // 16 MB scratch
__device__ float g_rowsum[NROWS];

// ---------------------------------------------------------------------------
// helpers
// ---------------------------------------------------------------------------
__device__ __forceinline__ void mma_bf16(float* c, const uint32_t* a, uint32_t b0, uint32_t b1) {
    asm volatile(
        "mma.sync.aligned.m16n8k16.row.col.f32.bf16.bf16.f32 "
        "{%0,%1,%2,%3}, {%4,%5,%6,%7}, {%8,%9}, {%0,%1,%2,%3};"
        : "+f"(c[0]), "+f"(c[1]), "+f"(c[2]), "+f"(c[3])
        : "r"(a[0]), "r"(a[1]), "r"(a[2]), "r"(a[3]), "r"(b0), "r"(b1));
}

__device__ __forceinline__ void split2(float x, float y, uint32_t& hi, uint32_t& lo) {
    __nv_bfloat16 bx = __float2bfloat16_rn(x), by = __float2bfloat16_rn(y);
    float rx = x - __bfloat162float(bx);
    float ry = y - __bfloat162float(by);
    __nv_bfloat162 h; h.x = bx; h.y = by;
    __nv_bfloat162 l = __floats2bfloat162_rn(rx, ry);
    hi = *reinterpret_cast<uint32_t*>(&h);
    lo = *reinterpret_cast<uint32_t*>(&l);
}

#define STRB 72          // smem row stride bytes (32 bf16 + pad)
#define BUF128 (128 * STRB)
#define BUF64  (64 * STRB)

__global__ void zero_rowsum_kernel() {
    g_rowsum[blockIdx.x * 256 + threadIdx.x] = 0.f;
}

// ---------------------------------------------------------------------------
// C[M,N] = A[M,K] @ W[N,K]^T + bias.  Block 128x128, BK=32, 8 warps (2x4).
// Single-buffer smem (R3 exact — known good occupancy).
// ---------------------------------------------------------------------------
__global__ void __launch_bounds__(256) mma_gemm_bias(
    const float* __restrict__ A, const float* __restrict__ W,
    const float* __restrict__ bias, float* __restrict__ C, int N, int K)
{
    __shared__ __align__(16) char sAh[BUF128];
    __shared__ __align__(16) char sAl[BUF128];
    __shared__ __align__(16) char sBh[BUF128];
    __shared__ __align__(16) char sBl[BUF128];

    const int tid = threadIdx.x;
    const int lane = tid & 31, wid = tid >> 5;
    const int warp_m = wid >> 2, warp_n = wid & 3;
    const int bm = blockIdx.y * 128, bn = blockIdx.x * 128;
    const int row = tid >> 1, kq = (tid & 1) * 16;
    const int r4 = lane >> 2, c4 = lane & 3;

    float acc[4][4][4];
#pragma unroll
    for (int i = 0; i < 4; i++)
#pragma unroll
        for (int j = 0; j < 4; j++)
#pragma unroll
            for (int l = 0; l < 4; l++) acc[i][j][l] = 0.f;

    for (int kt = 0; kt < (K >> 5); kt++) {
        const float* Ap = A + (size_t)(bm + row) * K + kt * 32 + kq;
        const float* Wp = W + (size_t)(bn + row) * K + kt * 32 + kq;
        float4 av[4], wv[4];
#pragma unroll
        for (int i = 0; i < 4; i++) av[i] = *(const float4*)(Ap + i * 4);
#pragma unroll
        for (int i = 0; i < 4; i++) wv[i] = *(const float4*)(Wp + i * 4);
        __syncthreads();
#pragma unroll
        for (int i = 0; i < 4; i++) {
            uint32_t h0, l0, h1, l1;
            split2(av[i].x, av[i].y, h0, l0);
            split2(av[i].z, av[i].w, h1, l1);
            uint32_t off = row * STRB + (kq + i * 4) * 2;
            *(uint2*)(sAh + off) = make_uint2(h0, h1);
            *(uint2*)(sAl + off) = make_uint2(l0, l1);
            split2(wv[i].x, wv[i].y, h0, l0);
            split2(wv[i].z, wv[i].w, h1, l1);
            *(uint2*)(sBh + off) = make_uint2(h0, h1);
            *(uint2*)(sBl + off) = make_uint2(l0, l1);
        }
        __syncthreads();

#pragma unroll
        for (int s = 0; s < 2; s++) {
            const int kb = s * 32;
            uint32_t Ah[4][4], Al[4][4];
#pragma unroll
            for (int fm = 0; fm < 4; fm++) {
                uint32_t base = (warp_m * 64 + fm * 16 + r4) * STRB + kb + c4 * 4;
                Ah[fm][0] = *(const uint32_t*)(sAh + base);
                Ah[fm][1] = *(const uint32_t*)(sAh + base + 8 * STRB);
                Ah[fm][2] = *(const uint32_t*)(sAh + base + 16);
                Ah[fm][3] = *(const uint32_t*)(sAh + base + 8 * STRB + 16);
                Al[fm][0] = *(const uint32_t*)(sAl + base);
                Al[fm][1] = *(const uint32_t*)(sAl + base + 8 * STRB);
                Al[fm][2] = *(const uint32_t*)(sAl + base + 16);
                Al[fm][3] = *(const uint32_t*)(sAl + base + 8 * STRB + 16);
            }
#pragma unroll
            for (int fn = 0; fn < 4; fn++) {
                uint32_t bb = (warp_n * 32 + fn * 8 + r4) * STRB + kb + c4 * 4;
                uint32_t Bh0 = *(const uint32_t*)(sBh + bb);
                uint32_t Bh1 = *(const uint32_t*)(sBh + bb + 16);
                uint32_t Bl0 = *(const uint32_t*)(sBl + bb);
                uint32_t Bl1 = *(const uint32_t*)(sBl + bb + 16);
#pragma unroll
                for (int fm = 0; fm < 4; fm++) {
                    mma_bf16(acc[fm][fn], Ah[fm], Bh0, Bh1);
                    mma_bf16(acc[fm][fn], Ah[fm], Bl0, Bl1);
                    mma_bf16(acc[fm][fn], Al[fm], Bh0, Bh1);
                }
            }
        }
    }

    const int cq = c4 * 2;
#pragma unroll
    for (int fm = 0; fm < 4; fm++) {
#pragma unroll
        for (int fn = 0; fn < 4; fn++) {
            int row0 = bm + warp_m * 64 + fm * 16 + r4;
            int col  = bn + warp_n * 32 + fn * 8 + cq;
            float b0 = bias[col], b1 = bias[col + 1];
            *(float2*)(C + (size_t)row0 * N + col) =
                make_float2(acc[fm][fn][0] + b0, acc[fm][fn][1] + b1);
            *(float2*)(C + (size_t)(row0 + 8) * N + col) =
                make_float2(acc[fm][fn][2] + b0, acc[fm][fn][3] + b1);
        }
    }
}

// ---------------------------------------------------------------------------
// Scores + exp: E = exp(0.125 * Q K^T), atomic row sums.
// R3 single-buffer body + exp epilogue.
// ---------------------------------------------------------------------------
__global__ void __launch_bounds__(256) mma_scores_exp(
    const float* __restrict__ qkv, float* __restrict__ attn)
{
    __shared__ __align__(16) char sAh[BUF128];
    __shared__ __align__(16) char sAl[BUF128];
    __shared__ __align__(16) char sBh[BUF128];
    __shared__ __align__(16) char sBl[BUF128];

    const int tid = threadIdx.x;
    const int lane = tid & 31, wid = tid >> 5;
    const int warp_m = wid >> 2, warp_n = wid & 3;
    const int z = blockIdx.z, b = z >> 4, h = z & 15;
    const int bm = blockIdx.y * 128, bn = blockIdx.x * 128;
    const float* Qb = qkv + (size_t)b * SEQ * QKVF + h * HD;
    const float* Kb = Qb + EMB;
    float* Cb = attn + (size_t)z * SEQ * SEQ;
    const int row = tid >> 1, kq = (tid & 1) * 16;
    const int r4 = lane >> 2, c4 = lane & 3;

    float acc[4][4][4];
#pragma unroll
    for (int i = 0; i < 4; i++)
#pragma unroll
        for (int j = 0; j < 4; j++)
#pragma unroll
            for (int l = 0; l < 4; l++) acc[i][j][l] = 0.f;

#pragma unroll
    for (int kt = 0; kt < 2; kt++) {
        const float* Ap = Qb + (size_t)(bm + row) * QKVF + kt * 32 + kq;
        const float* Bp = Kb + (size_t)(bn + row) * QKVF + kt * 32 + kq;
        float4 av[4], wv[4];
#pragma unroll
        for (int i = 0; i < 4; i++) av[i] = *(const float4*)(Ap + i * 4);
#pragma unroll
        for (int i = 0; i < 4; i++) wv[i] = *(const float4*)(Bp + i * 4);
        __syncthreads();
#pragma unroll
        for (int i = 0; i < 4; i++) {
            uint32_t h0, l0, h1, l1;
            split2(av[i].x, av[i].y, h0, l0);
            split2(av[i].z, av[i].w, h1, l1);
            uint32_t off = row * STRB + (kq + i * 4) * 2;
            *(uint2*)(sAh + off) = make_uint2(h0, h1);
            *(uint2*)(sAl + off) = make_uint2(l0, l1);
            split2(wv[i].x, wv[i].y, h0, l0);
            split2(wv[i].z, wv[i].w, h1, l1);
            *(uint2*)(sBh + off) = make_uint2(h0, h1);
            *(uint2*)(sBl + off) = make_uint2(l0, l1);
        }
        __syncthreads();

#pragma unroll
        for (int s = 0; s < 2; s++) {
            const int kb = s * 32;
            uint32_t Ah[4][4], Al[4][4];
#pragma unroll
            for (int fm = 0; fm < 4; fm++) {
                uint32_t base = (warp_m * 64 + fm * 16 + r4) * STRB + kb + c4 * 4;
                Ah[fm][0] = *(const uint32_t*)(sAh + base);
                Ah[fm][1] = *(const uint32_t*)(sAh + base + 8 * STRB);
                Ah[fm][2] = *(const uint32_t*)(sAh + base + 16);
                Ah[fm][3] = *(const uint32_t*)(sAh + base + 8 * STRB + 16);
                Al[fm][0] = *(const uint32_t*)(sAl + base);
                Al[fm][1] = *(const uint32_t*)(sAl + base + 8 * STRB);
                Al[fm][2] = *(const uint32_t*)(sAl + base + 16);
                Al[fm][3] = *(const uint32_t*)(sAl + base + 8 * STRB + 16);
            }
#pragma unroll
            for (int fn = 0; fn < 4; fn++) {
                uint32_t bb = (warp_n * 32 + fn * 8 + r4) * STRB + kb + c4 * 4;
                uint32_t Bh0 = *(const uint32_t*)(sBh + bb);
                uint32_t Bh1 = *(const uint32_t*)(sBh + bb + 16);
                uint32_t Bl0 = *(const uint32_t*)(sBl + bb);
                uint32_t Bl1 = *(const uint32_t*)(sBl + bb + 16);
#pragma unroll
                for (int fm = 0; fm < 4; fm++) {
                    mma_bf16(acc[fm][fn], Ah[fm], Bh0, Bh1);
                    mma_bf16(acc[fm][fn], Ah[fm], Bl0, Bl1);
                    mma_bf16(acc[fm][fn], Al[fm], Bh0, Bh1);
                }
            }
        }
    }

    // epilogue: exp, store E, row-sum atomics
#pragma unroll
    for (int fm = 0; fm < 4; fm++) {
        const int row0 = bm + warp_m * 64 + fm * 16 + r4;
        float rs0 = 0.f, rs1 = 0.f;
#pragma unroll
        for (int fn = 0; fn < 4; fn++) {
            float e0 = __expf(acc[fm][fn][0] * 0.125f);
            float e1 = __expf(acc[fm][fn][1] * 0.125f);
            float e2 = __expf(acc[fm][fn][2] * 0.125f);
            float e3 = __expf(acc[fm][fn][3] * 0.125f);
            rs0 += e0 + e1;
            rs1 += e2 + e3;
            int col = bn + warp_n * 32 + fn * 8 + c4 * 2;
            *(float2*)(Cb + (size_t)row0 * SEQ + col)       = make_float2(e0, e1);
            *(float2*)(Cb + (size_t)(row0 + 8) * SEQ + col) = make_float2(e2, e3);
        }
        rs0 += __shfl_xor_sync(0xffffffffu, rs0, 1);
        rs0 += __shfl_xor_sync(0xffffffffu, rs0, 2);
        rs1 += __shfl_xor_sync(0xffffffffu, rs1, 1);
        rs1 += __shfl_xor_sync(0xffffffffu, rs1, 2);
        if (c4 == 0) {
            atomicAdd(&g_rowsum[(size_t)z * SEQ + row0], rs0);
            atomicAdd(&g_rowsum[(size_t)z * SEQ + row0 + 8], rs1);
        }
    }
}

// ---------------------------------------------------------------------------
// AV + normalize: loader reads E, scales by 1/rowsum, writes P back to gmem,
// stages P for MMA. O = P @ V. Block 128x64, BK=32, 8 warps (4x2).
// Double-buffered (R8 structure, measured fastest for av).
// ---------------------------------------------------------------------------
__global__ void __launch_bounds__(256) mma_av_norm(
    float* __restrict__ attn, const float* __restrict__ qkv,
    float* __restrict__ out)
{
    __shared__ __align__(16) char sAh[2 * BUF128];
    __shared__ __align__(16) char sAl[2 * BUF128];
    __shared__ __align__(16) char sBh[2 * BUF64];
    __shared__ __align__(16) char sBl[2 * BUF64];

    const int tid = threadIdx.x;
    const int lane = tid & 31, wid = tid >> 5;
    const int warp_m = wid >> 1, warp_n = wid & 1;
    const int z = blockIdx.y, b = z >> 4, h = z & 15;
    const int bm = blockIdx.x * 128;
    float* P = attn + (size_t)z * SEQ * SEQ;
    const float* V = qkv + (size_t)b * SEQ * QKVF + 2 * EMB + h * HD;
    float* O = out + (size_t)b * SEQ * EMB + h * HD;
    const int row = tid >> 1, kq = (tid & 1) * 16;
    const int vt = tid >> 3, vd = (tid & 7) * 8;
    const int r4 = lane >> 2, c4 = lane & 3;

    const float inv_l = __frcp_rn(g_rowsum[(size_t)z * SEQ + bm + row]);

    float acc[2][4][4];
#pragma unroll
    for (int i = 0; i < 2; i++)
#pragma unroll
        for (int j = 0; j < 4; j++)
#pragma unroll
            for (int l = 0; l < 4; l++) acc[i][j][l] = 0.f;

    float* Pb = P + (size_t)(bm + row) * SEQ + kq;
    const float* Vb = V + (size_t)vt * QKVF + vd;

    float4 av[4], vv0, vv1;
#pragma unroll
    for (int i = 0; i < 4; i++) {
        av[i] = *(const float4*)(Pb + i * 4);
        av[i].x *= inv_l; av[i].y *= inv_l; av[i].z *= inv_l; av[i].w *= inv_l;
    }
#pragma unroll
    for (int i = 0; i < 4; i++) *(float4*)(Pb + i * 4) = av[i];   // P writeback tile 0
    vv0 = *(const float4*)(Vb);
    vv1 = *(const float4*)(Vb + 4);

    const int NIT = SEQ >> 5;
    for (int kt = 0; kt < NIT; kt++) {
        char* bAh = sAh + (kt & 1) * BUF128;
        char* bAl = sAl + (kt & 1) * BUF128;
        char* bBh = sBh + (kt & 1) * BUF64;
        char* bBl = sBl + (kt & 1) * BUF64;
#pragma unroll
        for (int i = 0; i < 4; i++) {
            uint32_t h0, l0, h1, l1;
            split2(av[i].x, av[i].y, h0, l0);
            split2(av[i].z, av[i].w, h1, l1);
            uint32_t off = row * STRB + (kq + i * 4) * 2;
            *(uint2*)(bAh + off) = make_uint2(h0, h1);
            *(uint2*)(bAl + off) = make_uint2(l0, l1);
        }
        {
            float vals[8] = {vv0.x, vv0.y, vv0.z, vv0.w, vv1.x, vv1.y, vv1.z, vv1.w};
#pragma unroll
            for (int j = 0; j < 8; j++) {
                int d = vd + j;
                __nv_bfloat16 bh = __float2bfloat16_rn(vals[j]);
                float rl = vals[j] - __bfloat162float(bh);
                *(__nv_bfloat16*)(bBh + d * STRB + vt * 2) = bh;
                *(__nv_bfloat16*)(bBl + d * STRB + vt * 2) = __float2bfloat16_rn(rl);
            }
        }
        __syncthreads();
        if (kt + 1 < NIT) {
#pragma unroll
            for (int i = 0; i < 4; i++) {
                av[i] = *(const float4*)(Pb + (kt + 1) * 32 + i * 4);
                av[i].x *= inv_l; av[i].y *= inv_l; av[i].z *= inv_l; av[i].w *= inv_l;
            }
#pragma unroll
            for (int i = 0; i < 4; i++) *(float4*)(Pb + (kt + 1) * 32 + i * 4) = av[i];
            vv0 = *(const float4*)(Vb + (size_t)(kt + 1) * 32 * QKVF);
            vv1 = *(const float4*)(Vb + (size_t)(kt + 1) * 32 * QKVF + 4);
        }

#pragma unroll
        for (int s = 0; s < 2; s++) {
            const int kb = s * 32;
            uint32_t Ah[2][4], Al[2][4];
#pragma unroll
            for (int fm = 0; fm < 2; fm++) {
                uint32_t base = (warp_m * 32 + fm * 16 + r4) * STRB + kb + c4 * 4;
                Ah[fm][0] = *(const uint32_t*)(bAh + base);
                Ah[fm][1] = *(const uint32_t*)(bAh + base + 8 * STRB);
                Ah[fm][2] = *(const uint32_t*)(bAh + base + 16);
                Ah[fm][3] = *(const uint32_t*)(bAh + base + 8 * STRB + 16);
                Al[fm][0] = *(const uint32_t*)(bAl + base);
                Al[fm][1] = *(const uint32_t*)(bAl + base + 8 * STRB);
                Al[fm][2] = *(const uint32_t*)(bAl + base + 16);
                Al[fm][3] = *(const uint32_t*)(bAl + base + 8 * STRB + 16);
            }
#pragma unroll
            for (int fn = 0; fn < 4; fn++) {
                uint32_t bb = (warp_n * 32 + fn * 8 + r4) * STRB + kb + c4 * 4;
                uint32_t Bh0 = *(const uint32_t*)(bBh + bb);
                uint32_t Bh1 = *(const uint32_t*)(bBh + bb + 16);
                uint32_t Bl0 = *(const uint32_t*)(bBl + bb);
                uint32_t Bl1 = *(const uint32_t*)(bBl + bb + 16);
#pragma unroll
                for (int fm = 0; fm < 2; fm++) {
                    mma_bf16(acc[fm][fn], Ah[fm], Bh0, Bh1);
                    mma_bf16(acc[fm][fn], Ah[fm], Bl0, Bl1);
                    mma_bf16(acc[fm][fn], Al[fm], Bh0, Bh1);
                }
            }
        }
    }

    const int cq = c4 * 2;
#pragma unroll
    for (int fm = 0; fm < 2; fm++) {
#pragma unroll
        for (int fn = 0; fn < 4; fn++) {
            int row0 = bm + warp_m * 32 + fm * 16 + r4;
            int col  = warp_n * 32 + fn * 8 + cq;
            *(float2*)(O + (size_t)row0 * EMB + col) =
                make_float2(acc[fm][fn][0], acc[fm][fn][1]);
            *(float2*)(O + (size_t)(row0 + 8) * EMB + col) =
                make_float2(acc[fm][fn][2], acc[fm][fn][3]);
        }
    }
}

// ---------------------------------------------------------------------------
extern "C" void kernel_launch(void* const* d_in, const int* in_sizes, int n_in,
                              void* d_out, int out_size)
{
    const float* x     = (const float*)d_in[0];
    const float* qkv_w = (const float*)d_in[1];
    const float* qkv_b = (const float*)d_in[2];
    const float* out_w = (const float*)d_in[3];
    const float* out_b = (const float*)d_in[4];

    float* out_proj = (float*)d_out;
    float* attn     = (float*)d_out + OUT_ELEMS;

    float* qkv = nullptr;
    float* ao  = nullptr;
    cudaGetSymbolAddress((void**)&qkv, g_qkv);
    cudaGetSymbolAddress((void**)&ao,  g_ao);

    // 1. QKV projection
    mma_gemm_bias<<<dim3(QKVF / 128, TOK / 128), 256>>>(x, qkv_w, qkv_b, qkv, QKVF, EMB);
    // 2. zero rowsums
    zero_rowsum_kernel<<<NROWS / 256, 256>>>();
    // 3. Scores + exp + rowsum atomics
    mma_scores_exp<<<dim3(SEQ / 128, SEQ / 128, BATCH * NH), 256>>>(qkv, attn);
    // 4. AV + normalize (P written back during staging)
    mma_av_norm<<<dim3(SEQ / 128, BATCH * NH), 256>>>(attn, qkv, ao);
    // 5. Output projection
    mma_gemm_bias<<<dim3(EMB / 128, TOK / 128), 256>>>(ao, out_w, out_b, out_proj, EMB, EMB);
}

// round 11
// speedup vs baseline: 1.2287x; 1.1022x over previous
#include <cuda_runtime.h>
#include <cuda_bf16.h>
#include <stdint.h>
#include <math_constants.h>

#define BATCH 2
#define SEQ   2048
#define EMB   1024
#define NH    16
#define HD    64
#define TOK   4096
#define QKVF  3072
#define NROWS (BATCH * NH * SEQ)
#define OUT_ELEMS ((size_t)TOK * EMB)

__device__ float g_qkv[(size_t)TOK * QKVF];   // 50 MB scratch
__device__ float g_ao [(size_t)TOK * EMB];    // 16 MB scratch
__device__ float g_rowsum[NROWS];

// ---------------------------------------------------------------------------
// helpers
// ---------------------------------------------------------------------------
__device__ __forceinline__ void mma_bf16(float* c, const uint32_t* a, uint32_t b0, uint32_t b1) {
    asm volatile(
        "mma.sync.aligned.m16n8k16.row.col.f32.bf16.bf16.f32 "
        "{%0,%1,%2,%3}, {%4,%5,%6,%7}, {%8,%9}, {%0,%1,%2,%3};"
        : "+f"(c[0]), "+f"(c[1]), "+f"(c[2]), "+f"(c[3])
        : "r"(a[0]), "r"(a[1]), "r"(a[2]), "r"(a[3]), "r"(b0), "r"(b1));
}

__device__ __forceinline__ void split2(float x, float y, uint32_t& hi, uint32_t& lo) {
    __nv_bfloat16 bx = __float2bfloat16_rn(x), by = __float2bfloat16_rn(y);
    float rx = x - __bfloat162float(bx);
    float ry = y - __bfloat162float(by);
    __nv_bfloat162 h; h.x = bx; h.y = by;
    __nv_bfloat162 l = __floats2bfloat162_rn(rx, ry);
    hi = *reinterpret_cast<uint32_t*>(&h);
    lo = *reinterpret_cast<uint32_t*>(&l);
}

#define STRB 80          // smem row stride bytes: 64B data + 16B pad (bank-clean)
#define BUF128 (128 * STRB)
#define BUF64  (64 * STRB)

__global__ void zero_rowsum_kernel() {
    g_rowsum[blockIdx.x * 256 + threadIdx.x] = 0.f;
}

// ---------------------------------------------------------------------------
// C[M,N] = A[M,K] @ W[N,K]^T + bias.  Block 128x128, BK=32, 8 warps (2x4).
// Single-buffer smem.
// ---------------------------------------------------------------------------
__global__ void __launch_bounds__(256) mma_gemm_bias(
    const float* __restrict__ A, const float* __restrict__ W,
    const float* __restrict__ bias, float* __restrict__ C, int N, int K)
{
    __shared__ __align__(16) char sAh[BUF128];
    __shared__ __align__(16) char sAl[BUF128];
    __shared__ __align__(16) char sBh[BUF128];
    __shared__ __align__(16) char sBl[BUF128];

    const int tid = threadIdx.x;
    const int lane = tid & 31, wid = tid >> 5;
    const int warp_m = wid >> 2, warp_n = wid & 3;
    const int bm = blockIdx.y * 128, bn = blockIdx.x * 128;
    const int row = tid >> 1, kq = (tid & 1) * 16;
    const int r4 = lane >> 2, c4 = lane & 3;

    float acc[4][4][4];
#pragma unroll
    for (int i = 0; i < 4; i++)
#pragma unroll
        for (int j = 0; j < 4; j++)
#pragma unroll
            for (int l = 0; l < 4; l++) acc[i][j][l] = 0.f;

    for (int kt = 0; kt < (K >> 5); kt++) {
        const float* Ap = A + (size_t)(bm + row) * K + kt * 32 + kq;
        const float* Wp = W + (size_t)(bn + row) * K + kt * 32 + kq;
        float4 av[4], wv[4];
#pragma unroll
        for (int i = 0; i < 4; i++) av[i] = *(const float4*)(Ap + i * 4);
#pragma unroll
        for (int i = 0; i < 4; i++) wv[i] = *(const float4*)(Wp + i * 4);
        __syncthreads();
#pragma unroll
        for (int i = 0; i < 4; i++) {
            uint32_t h0, l0, h1, l1;
            split2(av[i].x, av[i].y, h0, l0);
            split2(av[i].z, av[i].w, h1, l1);
            uint32_t off = row * STRB + (kq + i * 4) * 2;
            *(uint2*)(sAh + off) = make_uint2(h0, h1);
            *(uint2*)(sAl + off) = make_uint2(l0, l1);
            split2(wv[i].x, wv[i].y, h0, l0);
            split2(wv[i].z, wv[i].w, h1, l1);
            *(uint2*)(sBh + off) = make_uint2(h0, h1);
            *(uint2*)(sBl + off) = make_uint2(l0, l1);
        }
        __syncthreads();

#pragma unroll
        for (int s = 0; s < 2; s++) {
            const int kb = s * 32;
            uint32_t Ah[4][4], Al[4][4];
#pragma unroll
            for (int fm = 0; fm < 4; fm++) {
                uint32_t base = (warp_m * 64 + fm * 16 + r4) * STRB + kb + c4 * 4;
                Ah[fm][0] = *(const uint32_t*)(sAh + base);
                Ah[fm][1] = *(const uint32_t*)(sAh + base + 8 * STRB);
                Ah[fm][2] = *(const uint32_t*)(sAh + base + 16);
                Ah[fm][3] = *(const uint32_t*)(sAh + base + 8 * STRB + 16);
                Al[fm][0] = *(const uint32_t*)(sAl + base);
                Al[fm][1] = *(const uint32_t*)(sAl + base + 8 * STRB);
                Al[fm][2] = *(const uint32_t*)(sAl + base + 16);
                Al[fm][3] = *(const uint32_t*)(sAl + base + 8 * STRB + 16);
            }
#pragma unroll
            for (int fn = 0; fn < 4; fn++) {
                uint32_t bb = (warp_n * 32 + fn * 8 + r4) * STRB + kb + c4 * 4;
                uint32_t Bh0 = *(const uint32_t*)(sBh + bb);
                uint32_t Bh1 = *(const uint32_t*)(sBh + bb + 16);
                uint32_t Bl0 = *(const uint32_t*)(sBl + bb);
                uint32_t Bl1 = *(const uint32_t*)(sBl + bb + 16);
#pragma unroll
                for (int fm = 0; fm < 4; fm++) {
                    mma_bf16(acc[fm][fn], Ah[fm], Bh0, Bh1);
                    mma_bf16(acc[fm][fn], Ah[fm], Bl0, Bl1);
                    mma_bf16(acc[fm][fn], Al[fm], Bh0, Bh1);
                }
            }
        }
    }

    const int cq = c4 * 2;
#pragma unroll
    for (int fm = 0; fm < 4; fm++) {
#pragma unroll
        for (int fn = 0; fn < 4; fn++) {
            int row0 = bm + warp_m * 64 + fm * 16 + r4;
            int col  = bn + warp_n * 32 + fn * 8 + cq;
            float b0 = bias[col], b1 = bias[col + 1];
            *(float2*)(C + (size_t)row0 * N + col) =
                make_float2(acc[fm][fn][0] + b0, acc[fm][fn][1] + b1);
            *(float2*)(C + (size_t)(row0 + 8) * N + col) =
                make_float2(acc[fm][fn][2] + b0, acc[fm][fn][3] + b1);
        }
    }
}

// ---------------------------------------------------------------------------
// Scores + exp: E = exp(0.125 * Q K^T), atomic row sums.
// ---------------------------------------------------------------------------
__global__ void __launch_bounds__(256) mma_scores_exp(
    const float* __restrict__ qkv, float* __restrict__ attn)
{
    __shared__ __align__(16) char sAh[BUF128];
    __shared__ __align__(16) char sAl[BUF128];
    __shared__ __align__(16) char sBh[BUF128];
    __shared__ __align__(16) char sBl[BUF128];

    const int tid = threadIdx.x;
    const int lane = tid & 31, wid = tid >> 5;
    const int warp_m = wid >> 2, warp_n = wid & 3;
    const int z = blockIdx.z, b = z >> 4, h = z & 15;
    const int bm = blockIdx.y * 128, bn = blockIdx.x * 128;
    const float* Qb = qkv + (size_t)b * SEQ * QKVF + h * HD;
    const float* Kb = Qb + EMB;
    float* Cb = attn + (size_t)z * SEQ * SEQ;
    const int row = tid >> 1, kq = (tid & 1) * 16;
    const int r4 = lane >> 2, c4 = lane & 3;

    float acc[4][4][4];
#pragma unroll
    for (int i = 0; i < 4; i++)
#pragma unroll
        for (int j = 0; j < 4; j++)
#pragma unroll
            for (int l = 0; l < 4; l++) acc[i][j][l] = 0.f;

#pragma unroll
    for (int kt = 0; kt < 2; kt++) {
        const float* Ap = Qb + (size_t)(bm + row) * QKVF + kt * 32 + kq;
        const float* Bp = Kb + (size_t)(bn + row) * QKVF + kt * 32 + kq;
        float4 av[4], wv[4];
#pragma unroll
        for (int i = 0; i < 4; i++) av[i] = *(const float4*)(Ap + i * 4);
#pragma unroll
        for (int i = 0; i < 4; i++) wv[i] = *(const float4*)(Bp + i * 4);
        __syncthreads();
#pragma unroll
        for (int i = 0; i < 4; i++) {
            uint32_t h0, l0, h1, l1;
            split2(av[i].x, av[i].y, h0, l0);
            split2(av[i].z, av[i].w, h1, l1);
            uint32_t off = row * STRB + (kq + i * 4) * 2;
            *(uint2*)(sAh + off) = make_uint2(h0, h1);
            *(uint2*)(sAl + off) = make_uint2(l0, l1);
            split2(wv[i].x, wv[i].y, h0, l0);
            split2(wv[i].z, wv[i].w, h1, l1);
            *(uint2*)(sBh + off) = make_uint2(h0, h1);
            *(uint2*)(sBl + off) = make_uint2(l0, l1);
        }
        __syncthreads();

#pragma unroll
        for (int s = 0; s < 2; s++) {
            const int kb = s * 32;
            uint32_t Ah[4][4], Al[4][4];
#pragma unroll
            for (int fm = 0; fm < 4; fm++) {
                uint32_t base = (warp_m * 64 + fm * 16 + r4) * STRB + kb + c4 * 4;
                Ah[fm][0] = *(const uint32_t*)(sAh + base);
                Ah[fm][1] = *(const uint32_t*)(sAh + base + 8 * STRB);
                Ah[fm][2] = *(const uint32_t*)(sAh + base + 16);
                Ah[fm][3] = *(const uint32_t*)(sAh + base + 8 * STRB + 16);
                Al[fm][0] = *(const uint32_t*)(sAl + base);
                Al[fm][1] = *(const uint32_t*)(sAl + base + 8 * STRB);
                Al[fm][2] = *(const uint32_t*)(sAl + base + 16);
                Al[fm][3] = *(const uint32_t*)(sAl + base + 8 * STRB + 16);
            }
#pragma unroll
            for (int fn = 0; fn < 4; fn++) {
                uint32_t bb = (warp_n * 32 + fn * 8 + r4) * STRB + kb + c4 * 4;
                uint32_t Bh0 = *(const uint32_t*)(sBh + bb);
                uint32_t Bh1 = *(const uint32_t*)(sBh + bb + 16);
                uint32_t Bl0 = *(const uint32_t*)(sBl + bb);
                uint32_t Bl1 = *(const uint32_t*)(sBl + bb + 16);
#pragma unroll
                for (int fm = 0; fm < 4; fm++) {
                    mma_bf16(acc[fm][fn], Ah[fm], Bh0, Bh1);
                    mma_bf16(acc[fm][fn], Ah[fm], Bl0, Bl1);
                    mma_bf16(acc[fm][fn], Al[fm], Bh0, Bh1);
                }
            }
        }
    }

    // epilogue: exp, store E, row-sum atomics
#pragma unroll
    for (int fm = 0; fm < 4; fm++) {
        const int row0 = bm + warp_m * 64 + fm * 16 + r4;
        float rs0 = 0.f, rs1 = 0.f;
#pragma unroll
        for (int fn = 0; fn < 4; fn++) {
            float e0 = __expf(acc[fm][fn][0] * 0.125f);
            float e1 = __expf(acc[fm][fn][1] * 0.125f);
            float e2 = __expf(acc[fm][fn][2] * 0.125f);
            float e3 = __expf(acc[fm][fn][3] * 0.125f);
            rs0 += e0 + e1;
            rs1 += e2 + e3;
            int col = bn + warp_n * 32 + fn * 8 + c4 * 2;
            *(float2*)(Cb + (size_t)row0 * SEQ + col)       = make_float2(e0, e1);
            *(float2*)(Cb + (size_t)(row0 + 8) * SEQ + col) = make_float2(e2, e3);
        }
        rs0 += __shfl_xor_sync(0xffffffffu, rs0, 1);
        rs0 += __shfl_xor_sync(0xffffffffu, rs0, 2);
        rs1 += __shfl_xor_sync(0xffffffffu, rs1, 1);
        rs1 += __shfl_xor_sync(0xffffffffu, rs1, 2);
        if (c4 == 0) {
            atomicAdd(&g_rowsum[(size_t)z * SEQ + row0], rs0);
            atomicAdd(&g_rowsum[(size_t)z * SEQ + row0 + 8], rs1);
        }
    }
}

// ---------------------------------------------------------------------------
// AV + normalize, double-buffered, writeback AFTER the MMA section so the
// prefetch latency stays hidden. V staged pair-packed (4B STS).
// Block 128x64, BK=32, 8 warps (4x2).
// ---------------------------------------------------------------------------
__global__ void __launch_bounds__(256) mma_av_norm(
    float* __restrict__ attn, const float* __restrict__ qkv,
    float* __restrict__ out)
{
    __shared__ __align__(16) char sAh[2 * BUF128];
    __shared__ __align__(16) char sAl[2 * BUF128];
    __shared__ __align__(16) char sBh[2 * BUF64];
    __shared__ __align__(16) char sBl[2 * BUF64];

    const int tid = threadIdx.x;
    const int lane = tid & 31, wid = tid >> 5;
    const int warp_m = wid >> 1, warp_n = wid & 1;
    const int z = blockIdx.y, b = z >> 4, h = z & 15;
    const int bm = blockIdx.x * 128;
    float* P = attn + (size_t)z * SEQ * SEQ;
    const float* V = qkv + (size_t)b * SEQ * QKVF + 2 * EMB + h * HD;
    float* O = out + (size_t)b * SEQ * EMB + h * HD;
    const int row = tid >> 1, kq = (tid & 1) * 16;
    const int vt2 = tid & 15;            // t-pair index: rows 2*vt2, 2*vt2+1
    const int vd4 = (tid >> 4) * 4;      // d base (0..60 step 4)
    const int r4 = lane >> 2, c4 = lane & 3;

    const float inv_l = __frcp_rn(g_rowsum[(size_t)z * SEQ + bm + row]);

    float acc[2][4][4];
#pragma unroll
    for (int i = 0; i < 2; i++)
#pragma unroll
        for (int j = 0; j < 4; j++)
#pragma unroll
            for (int l = 0; l < 4; l++) acc[i][j][l] = 0.f;

    float* Pb = P + (size_t)(bm + row) * SEQ + kq;
    const float* Vb0 = V + (size_t)(2 * vt2) * QKVF + vd4;
    const float* Vb1 = V + (size_t)(2 * vt2 + 1) * QKVF + vd4;

    // prologue: tile 0 — load raw E, normalize, write P back
    float4 av[4], v0, v1;
#pragma unroll
    for (int i = 0; i < 4; i++) {
        av[i] = *(const float4*)(Pb + i * 4);
        av[i].x *= inv_l; av[i].y *= inv_l; av[i].z *= inv_l; av[i].w *= inv_l;
    }
#pragma unroll
    for (int i = 0; i < 4; i++) *(float4*)(Pb + i * 4) = av[i];
    v0 = *(const float4*)(Vb0);
    v1 = *(const float4*)(Vb1);

    const int NIT = SEQ >> 5;
    for (int kt = 0; kt < NIT; kt++) {
        char* bAh = sAh + (kt & 1) * BUF128;
        char* bAl = sAl + (kt & 1) * BUF128;
        char* bBh = sBh + (kt & 1) * BUF64;
        char* bBl = sBl + (kt & 1) * BUF64;
        // stage A (normalized P)
#pragma unroll
        for (int i = 0; i < 4; i++) {
            uint32_t h0, l0, h1, l1;
            split2(av[i].x, av[i].y, h0, l0);
            split2(av[i].z, av[i].w, h1, l1);
            uint32_t off = row * STRB + (kq + i * 4) * 2;
            *(uint2*)(bAh + off) = make_uint2(h0, h1);
            *(uint2*)(bAl + off) = make_uint2(l0, l1);
        }
        // stage V pair-packed: sB[d][t-pair], {t0,t1} in one 32-bit word
        {
            float a0[4] = {v0.x, v0.y, v0.z, v0.w};
            float a1[4] = {v1.x, v1.y, v1.z, v1.w};
#pragma unroll
            for (int j = 0; j < 4; j++) {
                int d = vd4 + j;
                __nv_bfloat16 h0 = __float2bfloat16_rn(a0[j]);
                __nv_bfloat16 h1 = __float2bfloat16_rn(a1[j]);
                __nv_bfloat162 hp; hp.x = h0; hp.y = h1;
                __nv_bfloat162 lp = __floats2bfloat162_rn(
                    a0[j] - __bfloat162float(h0), a1[j] - __bfloat162float(h1));
                *(uint32_t*)(bBh + d * STRB + vt2 * 4) = *reinterpret_cast<uint32_t*>(&hp);
                *(uint32_t*)(bBl + d * STRB + vt2 * 4) = *reinterpret_cast<uint32_t*>(&lp);
            }
        }
        __syncthreads();

        // prefetch next tile (raw E — scaled after MMAs)
        if (kt + 1 < NIT) {
#pragma unroll
            for (int i = 0; i < 4; i++) av[i] = *(const float4*)(Pb + (kt + 1) * 32 + i * 4);
            v0 = *(const float4*)(Vb0 + (size_t)(kt + 1) * 32 * QKVF);
            v1 = *(const float4*)(Vb1 + (size_t)(kt + 1) * 32 * QKVF);
        }

#pragma unroll
        for (int s = 0; s < 2; s++) {
            const int kb = s * 32;
            uint32_t Ah[2][4], Al[2][4];
#pragma unroll
            for (int fm = 0; fm < 2; fm++) {
                uint32_t base = (warp_m * 32 + fm * 16 + r4) * STRB + kb + c4 * 4;
                Ah[fm][0] = *(const uint32_t*)(bAh + base);
                Ah[fm][1] = *(const uint32_t*)(bAh + base + 8 * STRB);
                Ah[fm][2] = *(const uint32_t*)(bAh + base + 16);
                Ah[fm][3] = *(const uint32_t*)(bAh + base + 8 * STRB + 16);
                Al[fm][0] = *(const uint32_t*)(bAl + base);
                Al[fm][1] = *(const uint32_t*)(bAl + base + 8 * STRB);
                Al[fm][2] = *(const uint32_t*)(bAl + base + 16);
                Al[fm][3] = *(const uint32_t*)(bAl + base + 8 * STRB + 16);
            }
#pragma unroll
            for (int fn = 0; fn < 4; fn++) {
                uint32_t bb = (warp_n * 32 + fn * 8 + r4) * STRB + kb + c4 * 4;
                uint32_t Bh0 = *(const uint32_t*)(bBh + bb);
                uint32_t Bh1 = *(const uint32_t*)(bBh + bb + 16);
                uint32_t Bl0 = *(const uint32_t*)(bBl + bb);
                uint32_t Bl1 = *(const uint32_t*)(bBl + bb + 16);
#pragma unroll
                for (int fm = 0; fm < 2; fm++) {
                    mma_bf16(acc[fm][fn], Ah[fm], Bh0, Bh1);
                    mma_bf16(acc[fm][fn], Ah[fm], Bl0, Bl1);
                    mma_bf16(acc[fm][fn], Al[fm], Bh0, Bh1);
                }
            }
        }

        // normalize next tile + write P back (loads have landed during MMAs)
        if (kt + 1 < NIT) {
#pragma unroll
            for (int i = 0; i < 4; i++) {
                av[i].x *= inv_l; av[i].y *= inv_l; av[i].z *= inv_l; av[i].w *= inv_l;
            }
#pragma unroll
            for (int i = 0; i < 4; i++) *(float4*)(Pb + (kt + 1) * 32 + i * 4) = av[i];
        }
    }

    const int cq = c4 * 2;
#pragma unroll
    for (int fm = 0; fm < 2; fm++) {
#pragma unroll
        for (int fn = 0; fn < 4; fn++) {
            int row0 = bm + warp_m * 32 + fm * 16 + r4;
            int col  = warp_n * 32 + fn * 8 + cq;
            *(float2*)(O + (size_t)row0 * EMB + col) =
                make_float2(acc[fm][fn][0], acc[fm][fn][1]);
            *(float2*)(O + (size_t)(row0 + 8) * EMB + col) =
                make_float2(acc[fm][fn][2], acc[fm][fn][3]);
        }
    }
}

// ---------------------------------------------------------------------------
extern "C" void kernel_launch(void* const* d_in, const int* in_sizes, int n_in,
                              void* d_out, int out_size)
{
    const float* x     = (const float*)d_in[0];
    const float* qkv_w = (const float*)d_in[1];
    const float* qkv_b = (const float*)d_in[2];
    const float* out_w = (const float*)d_in[3];
    const float* out_b = (const float*)d_in[4];

    float* out_proj = (float*)d_out;
    float* attn     = (float*)d_out + OUT_ELEMS;

    float* qkv = nullptr;
    float* ao  = nullptr;
    cudaGetSymbolAddress((void**)&qkv, g_qkv);
    cudaGetSymbolAddress((void**)&ao,  g_ao);

    // 1. QKV projection
    mma_gemm_bias<<<dim3(QKVF / 128, TOK / 128), 256>>>(x, qkv_w, qkv_b, qkv, QKVF, EMB);
    // 2. zero rowsums
    zero_rowsum_kernel<<<NROWS / 256, 256>>>();
    // 3. Scores + exp + rowsum atomics
    mma_scores_exp<<<dim3(SEQ / 128, SEQ / 128, BATCH * NH), 256>>>(qkv, attn);
    // 4. AV + normalize (P written back after MMA section each iter)
    mma_av_norm<<<dim3(SEQ / 128, BATCH * NH), 256>>>(attn, qkv, ao);
    // 5. Output projection
    mma_gemm_bias<<<dim3(EMB / 128, TOK / 128), 256>>>(ao, out_w, out_b, out_proj, EMB, EMB);
}